// round 9
// baseline (speedup 1.0000x reference)
#include <cuda_runtime.h>
#include <math.h>
#include <stdint.h>

// GRU T=512, B=32, D=H=1024, fp32. Persistent kernel, 147 CTAs (1/SM), JT=7.
// f32x2 packed FMA; h read directly from L2 (__ldcg float2, [k][b] layout).
// Warp = 16 b-pairs x 2 k-subgroups: one LDS.128 of W serves both subgroups
// (adjacent 16B lines) and 2 batch rows -> W-LDS per FFMA2 halved vs r8.

#define TT   512
#define BB   32
#define DD   1024
#define HH   1024
#define NCTA 147
#define JT   7
#define NC   21
#define NTH  512
#define NW   16
#define RSTR 21
#define NBLK 32                    // reduction blocks (16 warps x 2 ksub)
#define BLKSTR 673                 // 32*RSTR + 1 (bank-disjoint halves)

#define TBH (TT * BB * HH)
#define BH  (BB * HH)
#define G3H (3 * HH)

#define WS_FLOATS  (NC * DD)                   // 21504
#define RED_FLOATS (NBLK * BLKSTR)             // 21536
#define SMEM_BYTES ((WS_FLOATS + RED_FLOATS) * 4)  // 172160

typedef unsigned long long u64;

__device__ float g_xT[(size_t)TT * BH];        // [t][k][b]
__device__ float g_WT[2][(size_t)G3H * DD];    // [m][c][k]
__device__ float g_Gi[(size_t)TT * NCTA * 3 * 224];
__device__ float g_h[2 * BH];                  // [buf][k][b]
__device__ unsigned int g_bar;

static __device__ __forceinline__ void fma2(u64 &d, u64 a, u64 b) {
    asm("fma.rn.f32x2 %0, %1, %2, %0;" : "+l"(d) : "l"(a), "l"(b));
}
static __device__ __forceinline__ u64 packf2(float lo, float hi) {
    u64 r; asm("mov.b64 %0, {%1, %2};" : "=l"(r) : "f"(lo), "f"(hi)); return r;
}
static __device__ __forceinline__ float2 unpackf2(u64 v) {
    float2 r; asm("mov.b64 {%0, %1}, %2;" : "=f"(r.x), "=f"(r.y) : "l"(v)); return r;
}
static __device__ __forceinline__ float sigmoidf_(float x) {
    return 1.0f / (1.0f + __expf(-x));
}

// ---------------- prep kernels ----------------
__global__ void wtrans_kernel(const float* __restrict__ W0, const float* __restrict__ W1) {
    __shared__ float s[32][33];
    const float* W = blockIdx.z ? W1 : W0;
    float* WT = g_WT[blockIdx.z];
    int c0 = blockIdx.y * 32, k0 = blockIdx.x * 32;
    int tx = threadIdx.x, ty = threadIdx.y;
#pragma unroll
    for (int i = 0; i < 32; i += 8)
        s[ty + i][tx] = W[(size_t)(k0 + ty + i) * G3H + c0 + tx];
    __syncthreads();
#pragma unroll
    for (int i = 0; i < 32; i += 8)
        WT[(size_t)(c0 + ty + i) * DD + k0 + tx] = s[tx][ty + i];
}

__global__ void xtrans_kernel(const float* __restrict__ input) {
    __shared__ float s[32][33];
    int t = blockIdx.y, k0 = blockIdx.x * 32;
    int tx = threadIdx.x, ty = threadIdx.y;
    const float* xin = input + (size_t)t * BH;
    float* xo = g_xT + (size_t)t * BH;
#pragma unroll
    for (int i = 0; i < 32; i += 8)
        s[ty + i][tx] = xin[(size_t)(ty + i) * DD + k0 + tx];
    __syncthreads();
#pragma unroll
    for (int i = 0; i < 32; i += 8)
        xo[(size_t)(k0 + ty + i) * BB + tx] = s[tx][ty + i];
}

__global__ void zero_kernel() {
    int i = blockIdx.x * blockDim.x + threadIdx.x;
    if (i == 0) g_bar = 0u;
    if (i < 2 * BH) g_h[i] = 0.0f;
}

// ---------------- GEMM tile ----------------
// Thread: b0 = 2*bidx (and b0+1), k set = { kbase + 8i + u : i=0..7, u=0..3 },
// kbase = w*64 + 4*ksub. One LDS.128 per (c, i) serves both ksub groups.
// h loaded as float2 (b0,b0+1) straight from L2.
__device__ __forceinline__ void tile_gemm(const float* __restrict__ ws,
                                          const float* __restrict__ hg,
                                          int b0, int kbase, u64 (&acc)[2][NC]) {
#pragma unroll
    for (int c = 0; c < NC; c++) { acc[0][c] = 0ULL; acc[1][c] = 0ULL; }
    const float* hb = hg + (size_t)kbase * BB + b0;
    const float* wk = ws + kbase;
#pragma unroll 1
    for (int i = 0; i < 8; i++) {
        const float* hh = hb + (size_t)(8 * i) * BB;
        const float2 h0 = __ldcg((const float2*)(hh + 0 * BB));
        const float2 h1 = __ldcg((const float2*)(hh + 1 * BB));
        const float2 h2 = __ldcg((const float2*)(hh + 2 * BB));
        const float2 h3 = __ldcg((const float2*)(hh + 3 * BB));
        const u64 hp00 = packf2(h0.x, h1.x);   // b0, k/k+1
        const u64 hp01 = packf2(h2.x, h3.x);   // b0, k+2/k+3
        const u64 hp10 = packf2(h0.y, h1.y);   // b1
        const u64 hp11 = packf2(h2.y, h3.y);
        const float* wi = wk + 8 * i;
#pragma unroll
        for (int c = 0; c < NC; c++) {
            const ulonglong2 wv = *(const ulonglong2*)(wi + c * DD);
            fma2(acc[0][c], hp00, wv.x);
            fma2(acc[0][c], hp01, wv.y);
            fma2(acc[1][c], hp10, wv.x);
            fma2(acc[1][c], hp11, wv.y);
        }
    }
}

// ---------------- main persistent kernel ----------------
__global__ void __launch_bounds__(NTH, 1) gru_persistent(
    const float* __restrict__ paddings,
    const float* __restrict__ b_ih, const float* __restrict__ b_hh,
    float* __restrict__ out, int out_size)
{
    extern __shared__ float sm[];
    float* ws  = sm;                    // [NC][DD]
    float* red = sm + WS_FLOATS;        // [NBLK][BLKSTR]

    const int tid  = threadIdx.x;
    const int cta  = blockIdx.x;
    const int j0   = cta * JT;
    const int w    = tid >> 5;
    const int lane = tid & 31;
    const int bidx = lane & 15;
    const int ksub = lane >> 4;
    const int b0   = bidx * 2;
    const int kbase = w * 64 + 4 * ksub;
    const int blk  = w * 2 + ksub;

    const int gb = tid & 31;
    const int gj = tid >> 5;
    const int jg = j0 + gj;
    const bool gact = (gj < JT) && (jg < HH);
    const int jgc = (jg < HH) ? jg : (HH - 1);

    float bihr[3], bhhr[3];
#pragma unroll
    for (int g = 0; g < 3; g++) {
        bihr[g] = b_ih[g * HH + jgc];
        bhhr[g] = b_hh[g * HH + jgc];
    }

    // load W_ih slice: ws[c][k], c = jl*3 + g
    {
        const float* WT0 = g_WT[0];
        for (int idx = tid; idx < NC * (DD / 4); idx += NTH) {
            int c = idx >> 8, q = idx & 255;
            int g = c % 3, jl = c / 3;
            int j = j0 + jl; if (j > HH - 1) j = HH - 1;
            ((float4*)(ws + c * DD))[q] =
                ((const float4*)(WT0 + (size_t)(g * HH + j) * DD))[q];
        }
    }
    __syncthreads();

    // ================= Phase 1: Gi = X @ W_ih + b_ih =================
#pragma unroll 1
    for (int t = 0; t < TT; t++) {
        u64 acc[2][NC];
        tile_gemm(ws, g_xT + (size_t)t * BH, b0, kbase, acc);

        {
            float* myred = red + blk * BLKSTR + b0 * RSTR;
#pragma unroll
            for (int c = 0; c < NC; c++) {
                float2 u0 = unpackf2(acc[0][c]);
                float2 u1 = unpackf2(acc[1][c]);
                myred[c]        = u0.x + u0.y;
                myred[RSTR + c] = u1.x + u1.y;
            }
        }
        __syncthreads();

        if (gact) {
            float* gdst = g_Gi + ((size_t)t * NCTA + cta) * (3 * 224);
#pragma unroll
            for (int g = 0; g < 3; g++) {
                float s = bihr[g];
#pragma unroll
                for (int ww = 0; ww < NBLK; ww++)
                    s += red[ww * BLKSTR + gb * RSTR + gj * 3 + g];
                __stcg(&gdst[g * 224 + tid], s);
            }
        }
        __syncthreads();           // red reads done before next step's writes
    }

    // swap ws to W_hh
    {
        const float* WT1 = g_WT[1];
        for (int idx = tid; idx < NC * (DD / 4); idx += NTH) {
            int c = idx >> 8, q = idx & 255;
            int g = c % 3, jl = c / 3;
            int j = j0 + jl; if (j > HH - 1) j = HH - 1;
            ((float4*)(ws + c * DD))[q] =
                ((const float4*)(WT1 + (size_t)(g * HH + j) * DD))[q];
        }
    }
    __syncthreads();

    // ================= Phase 2: recurrence =================
    float h_old = 0.0f;
#pragma unroll 1
    for (int t = 0; t < TT; t++) {
        const int rb = t & 1;

        // prefetch Gi + padding (hidden behind gemm)
        float gi0 = 0.f, gi1 = 0.f, gi2 = 0.f, p = 0.f;
        if (gact) {
            const float* gsrc = g_Gi + ((size_t)t * NCTA + cta) * (3 * 224);
            gi0 = __ldcg(&gsrc[0 * 224 + tid]);
            gi1 = __ldcg(&gsrc[1 * 224 + tid]);
            gi2 = __ldcg(&gsrc[2 * 224 + tid]);
            p   = paddings[t * BB + gb];
        }

        u64 acc[2][NC];
        tile_gemm(ws, g_h + rb * BH, b0, kbase, acc);

        {
            float* myred = red + blk * BLKSTR + b0 * RSTR;
#pragma unroll
            for (int c = 0; c < NC; c++) {
                float2 u0 = unpackf2(acc[0][c]);
                float2 u1 = unpackf2(acc[1][c]);
                myred[c]        = u0.x + u0.y;
                myred[RSTR + c] = u1.x + u1.y;
            }
        }
        __syncthreads();

        if (gact) {
            float gh[3];
#pragma unroll
            for (int g = 0; g < 3; g++) {
                float s = bhhr[g];
#pragma unroll
                for (int ww = 0; ww < NBLK; ww++)
                    s += red[ww * BLKSTR + gb * RSTR + gj * 3 + g];
                gh[g] = s;
            }

            const float r = sigmoidf_(gi0 + gh[0]);
            const float z = sigmoidf_(gi1 + gh[1]);
            const float n = tanhf(gi2 + r * gh[2]);
            float hn = (1.0f - z) * n + z * h_old;
            hn = p * h_old + (1.0f - p) * hn;
            h_old = hn;

            out[(size_t)t * BH + gb * HH + jg] = hn;
            __stcg(&g_h[(1 - rb) * BH + jg * BB + gb], hn);
            if (t == TT - 1) {
                if (out_size >= TBH + BH)     out[TBH + gb * HH + jg] = hn;
                if (out_size >= TBH + 2 * BH) out[TBH + BH + gb * HH + jg] = hn;
            }
        }

        // ---- grid barrier (release h writes, arrive + spin) ----
        __threadfence();
        __syncthreads();
        if (t != TT - 1) {
            if (tid == 0) {
                atomicAdd(&g_bar, 1u);
                const unsigned int target = (unsigned int)(t + 1) * NCTA;
                while (*((volatile unsigned int*)&g_bar) < target) {
                    __nanosleep(32);
                }
                __threadfence();
            }
            __syncthreads();
        }
    }
}

extern "C" void kernel_launch(void* const* d_in, const int* in_sizes, int n_in,
                              void* d_out, int out_size) {
    const float* input    = (const float*)d_in[0];
    const float* paddings = (const float*)d_in[1];
    const float* W_ih     = (const float*)d_in[2];
    const float* W_hh     = (const float*)d_in[3];
    const float* b_ih     = (const float*)d_in[4];
    const float* b_hh     = (const float*)d_in[5];
    float* out = (float*)d_out;

    cudaFuncSetAttribute(gru_persistent,
                         cudaFuncAttributeMaxDynamicSharedMemorySize, SMEM_BYTES);

    {
        dim3 blk(32, 8);
        dim3 grd(DD / 32, G3H / 32, 2);
        wtrans_kernel<<<grd, blk>>>(W_ih, W_hh);
    }
    {
        dim3 blk(32, 8);
        dim3 grd(DD / 32, TT);
        xtrans_kernel<<<grd, blk>>>(input);
    }
    zero_kernel<<<(2 * BH + 255) / 256, 256>>>();

    gru_persistent<<<NCTA, NTH, SMEM_BYTES>>>(paddings, b_ih, b_hh, out, out_size);
}